// round 1
// baseline (speedup 1.0000x reference)
#include <cuda_runtime.h>
#include <cuda_bf16.h>

// ---------------------------------------------------------------------------
// Problem constants (shapes are fixed by the reference)
// ---------------------------------------------------------------------------
#define WB   4096          // windows (batch)
#define WN   49            // tokens per window
#define WC   512           // channels
#define WH   16            // heads
#define WHD  32            // head dim
#define WNW  64            // distinct masks
#define M_TOTAL (WB * WN)  // 200704 rows
#define SCALE 0.17677669529663687f  // 32^-0.5

// Scratch (allocation-free rule: __device__ globals)
__device__ float g_qkv[(size_t)M_TOTAL * (3 * WC)];   // [200704, 1536]
__device__ float g_att[(size_t)M_TOTAL * WC];         // [200704, 512]

// ---------------------------------------------------------------------------
// Kernel 1/3: SGEMM C = A[M,K] * B[K,N] + bias[N], fp32.
// BM=BN=128, BK=8, 256 threads, 8x8 per-thread tile. All dims divide tiles.
// ---------------------------------------------------------------------------
#define BM 128
#define BN 128
#define BK 8
#define TM 8
#define TN 8

__global__ void __launch_bounds__(256, 2)
gemm_bias_kernel(const float* __restrict__ A, const float* __restrict__ B,
                 const float* __restrict__ bias, float* __restrict__ C,
                 int M, int N, int K)
{
    __shared__ float As[BK][BM];
    __shared__ float Bs[BK][BN];

    const int t  = threadIdx.x;
    const int m0 = blockIdx.y * BM;
    const int n0 = blockIdx.x * BN;

    // A-tile load mapping: 128 rows x 8 k -> 256 threads x float4
    const int arow = t >> 1;            // 0..127
    const int acol = (t & 1) << 2;      // 0 or 4
    // B-tile load mapping: 8 rows x 128 cols -> 256 threads x float4
    const int brow = t >> 5;            // 0..7
    const int bcol = (t & 31) << 2;     // 0..124

    const int ty = t >> 4;              // 0..15
    const int tx = t & 15;              // 0..15

    float acc[TM][TN];
    #pragma unroll
    for (int i = 0; i < TM; i++)
        #pragma unroll
        for (int j = 0; j < TN; j++) acc[i][j] = 0.f;

    const float* Aptr = A + (size_t)(m0 + arow) * K + acol;
    const float* Bptr = B + (size_t)brow * N + n0 + bcol;

    for (int k0 = 0; k0 < K; k0 += BK) {
        float4 av = *reinterpret_cast<const float4*>(Aptr + k0);
        As[acol + 0][arow] = av.x;
        As[acol + 1][arow] = av.y;
        As[acol + 2][arow] = av.z;
        As[acol + 3][arow] = av.w;

        float4 bv = *reinterpret_cast<const float4*>(Bptr + (size_t)k0 * N);
        *reinterpret_cast<float4*>(&Bs[brow][bcol]) = bv;

        __syncthreads();

        #pragma unroll
        for (int k = 0; k < BK; k++) {
            float ra[TM], rb[TN];
            #pragma unroll
            for (int i = 0; i < TM; i++) ra[i] = As[k][ty * TM + i];
            #pragma unroll
            for (int j = 0; j < TN; j++) rb[j] = Bs[k][tx * TN + j];
            #pragma unroll
            for (int i = 0; i < TM; i++)
                #pragma unroll
                for (int j = 0; j < TN; j++)
                    acc[i][j] += ra[i] * rb[j];
        }
        __syncthreads();
    }

    // Epilogue: bias add + store (float4)
    #pragma unroll
    for (int i = 0; i < TM; i++) {
        const int m = m0 + ty * TM + i;
        float* crow = C + (size_t)m * N + n0 + tx * TN;
        const float* brow_ptr = bias + n0 + tx * TN;
        #pragma unroll
        for (int j = 0; j < TN; j += 4) {
            float4 cv;
            cv.x = acc[i][j + 0] + brow_ptr[j + 0];
            cv.y = acc[i][j + 1] + brow_ptr[j + 1];
            cv.z = acc[i][j + 2] + brow_ptr[j + 2];
            cv.w = acc[i][j + 3] + brow_ptr[j + 3];
            *reinterpret_cast<float4*>(crow + j) = cv;
        }
    }
}

// ---------------------------------------------------------------------------
// Kernel 2: per-(window, head) attention.
// grid = WB*WH CTAs, 128 threads. q/k/v + attn live in smem.
// Writes g_att[b*49+n][h*32+d] so proj is a plain GEMM.
// ---------------------------------------------------------------------------
__global__ void __launch_bounds__(128)
window_attn_kernel(const float* __restrict__ mask,          // [64,49,49]
                   const float* __restrict__ bias_table,    // [169,16]
                   const int*   __restrict__ pos_index)     // [49,49]
{
    __shared__ float sq[WN][WHD];
    __shared__ float sk[WN][WHD];
    __shared__ float sv[WN][WHD];
    __shared__ float sattn[WN][WN];

    const int bid = blockIdx.x;
    const int b   = bid >> 4;          // window
    const int h   = bid & 15;          // head
    const int t   = threadIdx.x;

    const float* qkv_base = g_qkv + (size_t)b * WN * (3 * WC) + h * WHD;

    // load q,k,v [49,32]
    for (int idx = t; idx < WN * WHD; idx += 128) {
        const int n = idx >> 5;        // token
        const int d = idx & 31;        // dim
        const float* row = qkv_base + (size_t)n * (3 * WC) + d;
        sq[n][d] = row[0];
        sk[n][d] = row[WC];
        sv[n][d] = row[2 * WC];
    }
    __syncthreads();

    // logits + bias + mask
    const float* mrow = mask + (size_t)(b & (WNW - 1)) * WN * WN;
    for (int e = t; e < WN * WN; e += 128) {
        const int i = e / WN;
        const int j = e - i * WN;
        float dot = 0.f;
        #pragma unroll
        for (int d = 0; d < WHD; d++) dot += sq[i][d] * sk[j][d];
        const float bq = bias_table[pos_index[e] * WH + h];
        sattn[i][j] = dot * SCALE + bq + mrow[e];
    }
    __syncthreads();

    // softmax: one warp per row
    const int warp = t >> 5, lane = t & 31;
    for (int i = warp; i < WN; i += 4) {
        float mx = -1e30f;
        for (int j = lane; j < WN; j += 32) mx = fmaxf(mx, sattn[i][j]);
        #pragma unroll
        for (int o = 16; o > 0; o >>= 1) mx = fmaxf(mx, __shfl_xor_sync(0xffffffffu, mx, o));
        float s = 0.f;
        for (int j = lane; j < WN; j += 32) {
            float e = expf(sattn[i][j] - mx);
            sattn[i][j] = e;
            s += e;
        }
        #pragma unroll
        for (int o = 16; o > 0; o >>= 1) s += __shfl_xor_sync(0xffffffffu, s, o);
        const float inv = 1.f / s;
        for (int j = lane; j < WN; j += 32) sattn[i][j] *= inv;
    }
    __syncthreads();

    // out = attn @ v ; write to g_att[b*49+i][h*32+d]
    for (int idx = t; idx < WN * WHD; idx += 128) {
        const int i = idx >> 5;
        const int d = idx & 31;
        float o = 0.f;
        #pragma unroll
        for (int j = 0; j < WN; j++) o += sattn[i][j] * sv[j][d];
        g_att[(size_t)(b * WN + i) * WC + h * WHD + d] = o;
    }
}

// ---------------------------------------------------------------------------
// Launch
// ---------------------------------------------------------------------------
extern "C" void kernel_launch(void* const* d_in, const int* in_sizes, int n_in,
                              void* d_out, int out_size)
{
    const float* x        = (const float*)d_in[0];   // [4096,49,512]
    const float* mask     = (const float*)d_in[1];   // [64,49,49]
    const float* w_qkv    = (const float*)d_in[2];   // [512,1536]
    const float* b_qkv    = (const float*)d_in[3];   // [1536]
    const float* w_proj   = (const float*)d_in[4];   // [512,512]
    const float* b_proj   = (const float*)d_in[5];   // [512]
    const float* pbt      = (const float*)d_in[6];   // [169,16]
    const int*   pos_idx  = (const int*)d_in[7];     // [49,49]
    float*       out      = (float*)d_out;           // [4096,49,512]

    float* qkv_buf;
    float* att_buf;
    cudaGetSymbolAddress((void**)&qkv_buf, g_qkv);
    cudaGetSymbolAddress((void**)&att_buf, g_att);

    // 1) qkv = x @ w_qkv + b_qkv   [200704,1536]
    {
        dim3 grid((3 * WC) / BN, M_TOTAL / BM);  // (12, 1568)
        gemm_bias_kernel<<<grid, 256>>>(x, w_qkv, b_qkv, qkv_buf,
                                        M_TOTAL, 3 * WC, WC);
    }

    // 2) per-(window, head) attention -> g_att [200704,512]
    {
        window_attn_kernel<<<WB * WH, 128>>>(mask, pbt, pos_idx);
    }

    // 3) out = g_att @ w_proj + b_proj  [200704,512]
    {
        dim3 grid(WC / BN, M_TOTAL / BM);        // (4, 1568)
        gemm_bias_kernel<<<grid, 256>>>(att_buf, w_proj, b_proj, out,
                                        M_TOTAL, WC, WC);
    }
}

// round 2
// speedup vs baseline: 1.8720x; 1.8720x over previous
#include <cuda_runtime.h>
#include <cuda_bf16.h>
#include <cstdint>

// ---------------------------------------------------------------------------
// Problem constants
// ---------------------------------------------------------------------------
#define WB   4096
#define WN   49
#define WC   512
#define WH   16
#define WHD  32
#define WNW  64
#define M_TOTAL (WB * WN)       // 200704
#define SCALE 0.17677669529663687f

// Scratch
__device__ float g_qkv[(size_t)M_TOTAL * (3 * WC)];
__device__ float g_att[(size_t)M_TOTAL * WC];

// ---------------------------------------------------------------------------
// TF32 tensor-core GEMM: C = A[M,K] @ B[K,N] + bias[N]
// CTA 128x128x16, 256 threads (8 warps, 2x4), warp tile 64x32,
// mma.sync m16n8k8 tf32, cp.async double-buffered smem.
// Requires M%128==0, N%128==0, K%16==0 (true for all our shapes).
// ---------------------------------------------------------------------------
#define BM 128
#define BN 128
#define BK 16
#define SA (BK + 4)    // 20 floats  — A smem row stride (conflict-free LDS)
#define SB (BN + 8)    // 136 floats — B smem row stride (conflict-free LDS)

__device__ __forceinline__ uint32_t f2tf32(float x) {
    uint32_t r;
    asm("cvt.rna.tf32.f32 %0, %1;" : "=r"(r) : "f"(x));
    return r;
}

__device__ __forceinline__ void cp16(uint32_t dst_smem, const float* src) {
    asm volatile("cp.async.cg.shared.global [%0], [%1], 16;"
                 :: "r"(dst_smem), "l"(src));
}

__device__ __forceinline__ void mma_tf32(float& c0, float& c1, float& c2, float& c3,
                                         uint32_t a0, uint32_t a1, uint32_t a2, uint32_t a3,
                                         uint32_t b0, uint32_t b1) {
    asm volatile(
        "mma.sync.aligned.m16n8k8.row.col.f32.tf32.tf32.f32 "
        "{%0,%1,%2,%3}, {%4,%5,%6,%7}, {%8,%9}, {%0,%1,%2,%3};"
        : "+f"(c0), "+f"(c1), "+f"(c2), "+f"(c3)
        : "r"(a0), "r"(a1), "r"(a2), "r"(a3), "r"(b0), "r"(b1));
}

__global__ void __launch_bounds__(256)
gemm_tf32_bias(const float* __restrict__ A, const float* __restrict__ B,
               const float* __restrict__ bias, float* __restrict__ C,
               int M, int N, int K)
{
    __shared__ float As[2][BM * SA];
    __shared__ float Bs[2][BK * SB];

    const int t    = threadIdx.x;
    const int warp = t >> 5;
    const int lane = t & 31;
    const int gid  = lane >> 2;   // 0..7
    const int tig  = lane & 3;    // 0..3

    const int m0 = blockIdx.y * BM;
    const int n0 = blockIdx.x * BN;

    const int wm = (warp >> 2) * 64;   // warp row offset in CTA tile
    const int wn = (warp & 3) * 32;    // warp col offset

    // --- global load mapping ---
    // A: two rows per thread (r, r+64), 4 consecutive k per thread
    const int ar  = t >> 2;            // 0..63
    const int ak  = (t & 3) * 4;       // 0,4,8,12
    // B: two rows per thread (br, br+8), 4 consecutive n per thread
    const int br  = t >> 5;            // 0..7
    const int bn  = (t & 31) * 4;      // 0..124

    const uint32_t sA_base = (uint32_t)__cvta_generic_to_shared(&As[0][0]);
    const uint32_t sB_base = (uint32_t)__cvta_generic_to_shared(&Bs[0][0]);
    const uint32_t sA_stage = BM * SA * 4u;
    const uint32_t sB_stage = BK * SB * 4u;

    const float* Ag = A + (size_t)(m0 + ar) * K + ak;
    const float* Bg = B + (size_t)br * N + n0 + bn;

    float acc[4][4][4];   // [mi][ni][c0..c3]
    #pragma unroll
    for (int mi = 0; mi < 4; mi++)
        #pragma unroll
        for (int ni = 0; ni < 4; ni++)
            #pragma unroll
            for (int c = 0; c < 4; c++) acc[mi][ni][c] = 0.f;

    const int iters = K / BK;

    // prologue: stage 0
    {
        cp16(sA_base + ((uint32_t)(ar * SA + ak) << 2),            Ag);
        cp16(sA_base + ((uint32_t)((ar + 64) * SA + ak) << 2),     Ag + (size_t)64 * K);
        cp16(sB_base + ((uint32_t)(br * SB + bn) << 2),            Bg);
        cp16(sB_base + ((uint32_t)((br + 8) * SB + bn) << 2),      Bg + (size_t)8 * N);
        asm volatile("cp.async.commit_group;");
    }

    for (int it = 0; it < iters; ++it) {
        asm volatile("cp.async.wait_group 0;");
        __syncthreads();

        if (it + 1 < iters) {
            const int k0 = (it + 1) * BK;
            const uint32_t st = ((it + 1) & 1);
            cp16(sA_base + st * sA_stage + ((uint32_t)(ar * SA + ak) << 2),
                 Ag + k0);
            cp16(sA_base + st * sA_stage + ((uint32_t)((ar + 64) * SA + ak) << 2),
                 Ag + (size_t)64 * K + k0);
            cp16(sB_base + st * sB_stage + ((uint32_t)(br * SB + bn) << 2),
                 Bg + (size_t)k0 * N);
            cp16(sB_base + st * sB_stage + ((uint32_t)((br + 8) * SB + bn) << 2),
                 Bg + (size_t)(k0 + 8) * N);
            asm volatile("cp.async.commit_group;");
        }

        const float* sA = As[it & 1];
        const float* sB = Bs[it & 1];

        #pragma unroll
        for (int kk = 0; kk < BK; kk += 8) {
            // A fragments: a0=A[gid][tig], a1=A[gid+8][tig], a2=A[gid][tig+4], a3=A[gid+8][tig+4]
            uint32_t af[4][4];
            #pragma unroll
            for (int mi = 0; mi < 4; mi++) {
                const int r = wm + mi * 16 + gid;
                af[mi][0] = f2tf32(sA[(r)     * SA + kk + tig]);
                af[mi][1] = f2tf32(sA[(r + 8) * SA + kk + tig]);
                af[mi][2] = f2tf32(sA[(r)     * SA + kk + tig + 4]);
                af[mi][3] = f2tf32(sA[(r + 8) * SA + kk + tig + 4]);
            }
            // B fragments: b0=B[tig][n], b1=B[tig+4][n], n = wn + ni*8 + gid
            uint32_t bf[4][2];
            #pragma unroll
            for (int ni = 0; ni < 4; ni++) {
                const int n = wn + ni * 8 + gid;
                bf[ni][0] = f2tf32(sB[(kk + tig)     * SB + n]);
                bf[ni][1] = f2tf32(sB[(kk + tig + 4) * SB + n]);
            }
            #pragma unroll
            for (int mi = 0; mi < 4; mi++)
                #pragma unroll
                for (int ni = 0; ni < 4; ni++)
                    mma_tf32(acc[mi][ni][0], acc[mi][ni][1],
                             acc[mi][ni][2], acc[mi][ni][3],
                             af[mi][0], af[mi][1], af[mi][2], af[mi][3],
                             bf[ni][0], bf[ni][1]);
        }
        // no trailing sync needed: next iter's wait+sync precedes buffer reuse
    }

    // epilogue: bias add + store (float2 per fragment half-row)
    #pragma unroll
    for (int mi = 0; mi < 4; mi++) {
        #pragma unroll
        for (int ni = 0; ni < 4; ni++) {
            const int col = n0 + wn + ni * 8 + tig * 2;
            const float b0 = bias[col];
            const float b1 = bias[col + 1];
            const int r0 = m0 + wm + mi * 16 + gid;
            float2 v0 = make_float2(acc[mi][ni][0] + b0, acc[mi][ni][1] + b1);
            float2 v1 = make_float2(acc[mi][ni][2] + b0, acc[mi][ni][3] + b1);
            *reinterpret_cast<float2*>(C + (size_t)r0 * N + col)       = v0;
            *reinterpret_cast<float2*>(C + (size_t)(r0 + 8) * N + col) = v1;
        }
    }
}

// ---------------------------------------------------------------------------
// Per-(window, head) attention (unchanged from R1)
// ---------------------------------------------------------------------------
__global__ void __launch_bounds__(128)
window_attn_kernel(const float* __restrict__ mask,
                   const float* __restrict__ bias_table,
                   const int*   __restrict__ pos_index)
{
    __shared__ float sq[WN][WHD];
    __shared__ float sk[WN][WHD];
    __shared__ float sv[WN][WHD];
    __shared__ float sattn[WN][WN];

    const int bid = blockIdx.x;
    const int b   = bid >> 4;
    const int h   = bid & 15;
    const int t   = threadIdx.x;

    const float* qkv_base = g_qkv + (size_t)b * WN * (3 * WC) + h * WHD;

    for (int idx = t; idx < WN * WHD; idx += 128) {
        const int n = idx >> 5;
        const int d = idx & 31;
        const float* row = qkv_base + (size_t)n * (3 * WC) + d;
        sq[n][d] = row[0];
        sk[n][d] = row[WC];
        sv[n][d] = row[2 * WC];
    }
    __syncthreads();

    const float* mrow = mask + (size_t)(b & (WNW - 1)) * WN * WN;
    for (int e = t; e < WN * WN; e += 128) {
        const int i = e / WN;
        const int j = e - i * WN;
        float dot = 0.f;
        #pragma unroll
        for (int d = 0; d < WHD; d++) dot += sq[i][d] * sk[j][d];
        const float bq = bias_table[pos_index[e] * WH + h];
        sattn[i][j] = dot * SCALE + bq + mrow[e];
    }
    __syncthreads();

    const int warp = t >> 5, lane = t & 31;
    for (int i = warp; i < WN; i += 4) {
        float mx = -1e30f;
        for (int j = lane; j < WN; j += 32) mx = fmaxf(mx, sattn[i][j]);
        #pragma unroll
        for (int o = 16; o > 0; o >>= 1) mx = fmaxf(mx, __shfl_xor_sync(0xffffffffu, mx, o));
        float s = 0.f;
        for (int j = lane; j < WN; j += 32) {
            float e = expf(sattn[i][j] - mx);
            sattn[i][j] = e;
            s += e;
        }
        #pragma unroll
        for (int o = 16; o > 0; o >>= 1) s += __shfl_xor_sync(0xffffffffu, s, o);
        const float inv = 1.f / s;
        for (int j = lane; j < WN; j += 32) sattn[i][j] *= inv;
    }
    __syncthreads();

    for (int idx = t; idx < WN * WHD; idx += 128) {
        const int i = idx >> 5;
        const int d = idx & 31;
        float o = 0.f;
        #pragma unroll
        for (int j = 0; j < WN; j++) o += sattn[i][j] * sv[j][d];
        g_att[(size_t)(b * WN + i) * WC + h * WHD + d] = o;
    }
}

// ---------------------------------------------------------------------------
// Launch
// ---------------------------------------------------------------------------
extern "C" void kernel_launch(void* const* d_in, const int* in_sizes, int n_in,
                              void* d_out, int out_size)
{
    const float* x       = (const float*)d_in[0];
    const float* mask    = (const float*)d_in[1];
    const float* w_qkv   = (const float*)d_in[2];
    const float* b_qkv   = (const float*)d_in[3];
    const float* w_proj  = (const float*)d_in[4];
    const float* b_proj  = (const float*)d_in[5];
    const float* pbt     = (const float*)d_in[6];
    const int*   pos_idx = (const int*)d_in[7];
    float*       out     = (float*)d_out;

    float* qkv_buf;
    float* att_buf;
    cudaGetSymbolAddress((void**)&qkv_buf, g_qkv);
    cudaGetSymbolAddress((void**)&att_buf, g_att);

    // 1) qkv = x @ w_qkv + b_qkv   [200704, 1536]
    {
        dim3 grid((3 * WC) / BN, M_TOTAL / BM);   // (12, 1568)
        gemm_tf32_bias<<<grid, 256>>>(x, w_qkv, b_qkv, qkv_buf,
                                      M_TOTAL, 3 * WC, WC);
    }

    // 2) attention -> g_att [200704, 512]
    window_attn_kernel<<<WB * WH, 128>>>(mask, pbt, pos_idx);

    // 3) out = g_att @ w_proj + b_proj  [200704, 512]
    {
        dim3 grid(WC / BN, M_TOTAL / BM);          // (4, 1568)
        gemm_tf32_bias<<<grid, 256>>>(att_buf, w_proj, b_proj, out,
                                      M_TOTAL, WC, WC);
    }
}

// round 3
// speedup vs baseline: 1.8733x; 1.0007x over previous
#include <cuda_runtime.h>
#include <cuda_bf16.h>
#include <cstdint>

// ---------------------------------------------------------------------------
// Problem constants
// ---------------------------------------------------------------------------
#define WB   4096
#define WN   49
#define WC   512
#define WH   16
#define WHD  32
#define WNW  64
#define M_TOTAL (WB * WN)       // 200704
#define SCALE 0.17677669529663687f

// Scratch
__device__ float g_qkv[(size_t)M_TOTAL * (3 * WC)];
__device__ float g_att[(size_t)M_TOTAL * WC];

// ---------------------------------------------------------------------------
// TF32 tensor-core GEMM: C = A[M,K] @ B[K,N] + bias[N]
// CTA 128x128x16, 256 threads (8 warps, 2x4), warp tile 64x32,
// mma.sync m16n8k8 tf32, cp.async double-buffered smem.
// Requires M%128==0, N%128==0, K%16==0 (true for all our shapes).
// ---------------------------------------------------------------------------
#define BM 128
#define BN 128
#define BK 16
#define SA (BK + 4)    // 20 floats  — A smem row stride (conflict-free LDS)
#define SB (BN + 8)    // 136 floats — B smem row stride (conflict-free LDS)

__device__ __forceinline__ uint32_t f2tf32(float x) {
    uint32_t r;
    asm("cvt.rna.tf32.f32 %0, %1;" : "=r"(r) : "f"(x));
    return r;
}

__device__ __forceinline__ void cp16(uint32_t dst_smem, const float* src) {
    asm volatile("cp.async.cg.shared.global [%0], [%1], 16;"
                 :: "r"(dst_smem), "l"(src));
}

__device__ __forceinline__ void mma_tf32(float& c0, float& c1, float& c2, float& c3,
                                         uint32_t a0, uint32_t a1, uint32_t a2, uint32_t a3,
                                         uint32_t b0, uint32_t b1) {
    asm volatile(
        "mma.sync.aligned.m16n8k8.row.col.f32.tf32.tf32.f32 "
        "{%0,%1,%2,%3}, {%4,%5,%6,%7}, {%8,%9}, {%0,%1,%2,%3};"
        : "+f"(c0), "+f"(c1), "+f"(c2), "+f"(c3)
        : "r"(a0), "r"(a1), "r"(a2), "r"(a3), "r"(b0), "r"(b1));
}

__global__ void __launch_bounds__(256)
gemm_tf32_bias(const float* __restrict__ A, const float* __restrict__ B,
               const float* __restrict__ bias, float* __restrict__ C,
               int M, int N, int K)
{
    __shared__ float As[2][BM * SA];
    __shared__ float Bs[2][BK * SB];

    const int t    = threadIdx.x;
    const int warp = t >> 5;
    const int lane = t & 31;
    const int gid  = lane >> 2;   // 0..7
    const int tig  = lane & 3;    // 0..3

    const int m0 = blockIdx.y * BM;
    const int n0 = blockIdx.x * BN;

    const int wm = (warp >> 2) * 64;   // warp row offset in CTA tile
    const int wn = (warp & 3) * 32;    // warp col offset

    // --- global load mapping ---
    // A: two rows per thread (r, r+64), 4 consecutive k per thread
    const int ar  = t >> 2;            // 0..63
    const int ak  = (t & 3) * 4;       // 0,4,8,12
    // B: two rows per thread (br, br+8), 4 consecutive n per thread
    const int br  = t >> 5;            // 0..7
    const int bn  = (t & 31) * 4;      // 0..124

    const uint32_t sA_base = (uint32_t)__cvta_generic_to_shared(&As[0][0]);
    const uint32_t sB_base = (uint32_t)__cvta_generic_to_shared(&Bs[0][0]);
    const uint32_t sA_stage = BM * SA * 4u;
    const uint32_t sB_stage = BK * SB * 4u;

    const float* Ag = A + (size_t)(m0 + ar) * K + ak;
    const float* Bg = B + (size_t)br * N + n0 + bn;

    float acc[4][4][4];   // [mi][ni][c0..c3]
    #pragma unroll
    for (int mi = 0; mi < 4; mi++)
        #pragma unroll
        for (int ni = 0; ni < 4; ni++)
            #pragma unroll
            for (int c = 0; c < 4; c++) acc[mi][ni][c] = 0.f;

    const int iters = K / BK;

    // prologue: stage 0
    {
        cp16(sA_base + ((uint32_t)(ar * SA + ak) << 2),            Ag);
        cp16(sA_base + ((uint32_t)((ar + 64) * SA + ak) << 2),     Ag + (size_t)64 * K);
        cp16(sB_base + ((uint32_t)(br * SB + bn) << 2),            Bg);
        cp16(sB_base + ((uint32_t)((br + 8) * SB + bn) << 2),      Bg + (size_t)8 * N);
        asm volatile("cp.async.commit_group;");
    }

    for (int it = 0; it < iters; ++it) {
        asm volatile("cp.async.wait_group 0;");
        __syncthreads();

        if (it + 1 < iters) {
            const int k0 = (it + 1) * BK;
            const uint32_t st = ((it + 1) & 1);
            cp16(sA_base + st * sA_stage + ((uint32_t)(ar * SA + ak) << 2),
                 Ag + k0);
            cp16(sA_base + st * sA_stage + ((uint32_t)((ar + 64) * SA + ak) << 2),
                 Ag + (size_t)64 * K + k0);
            cp16(sB_base + st * sB_stage + ((uint32_t)(br * SB + bn) << 2),
                 Bg + (size_t)k0 * N);
            cp16(sB_base + st * sB_stage + ((uint32_t)((br + 8) * SB + bn) << 2),
                 Bg + (size_t)(k0 + 8) * N);
            asm volatile("cp.async.commit_group;");
        }

        const float* sA = As[it & 1];
        const float* sB = Bs[it & 1];

        #pragma unroll
        for (int kk = 0; kk < BK; kk += 8) {
            // A fragments: a0=A[gid][tig], a1=A[gid+8][tig], a2=A[gid][tig+4], a3=A[gid+8][tig+4]
            uint32_t af[4][4];
            #pragma unroll
            for (int mi = 0; mi < 4; mi++) {
                const int r = wm + mi * 16 + gid;
                af[mi][0] = f2tf32(sA[(r)     * SA + kk + tig]);
                af[mi][1] = f2tf32(sA[(r + 8) * SA + kk + tig]);
                af[mi][2] = f2tf32(sA[(r)     * SA + kk + tig + 4]);
                af[mi][3] = f2tf32(sA[(r + 8) * SA + kk + tig + 4]);
            }
            // B fragments: b0=B[tig][n], b1=B[tig+4][n], n = wn + ni*8 + gid
            uint32_t bf[4][2];
            #pragma unroll
            for (int ni = 0; ni < 4; ni++) {
                const int n = wn + ni * 8 + gid;
                bf[ni][0] = f2tf32(sB[(kk + tig)     * SB + n]);
                bf[ni][1] = f2tf32(sB[(kk + tig + 4) * SB + n]);
            }
            #pragma unroll
            for (int mi = 0; mi < 4; mi++)
                #pragma unroll
                for (int ni = 0; ni < 4; ni++)
                    mma_tf32(acc[mi][ni][0], acc[mi][ni][1],
                             acc[mi][ni][2], acc[mi][ni][3],
                             af[mi][0], af[mi][1], af[mi][2], af[mi][3],
                             bf[ni][0], bf[ni][1]);
        }
        // no trailing sync needed: next iter's wait+sync precedes buffer reuse
    }

    // epilogue: bias add + store (float2 per fragment half-row)
    #pragma unroll
    for (int mi = 0; mi < 4; mi++) {
        #pragma unroll
        for (int ni = 0; ni < 4; ni++) {
            const int col = n0 + wn + ni * 8 + tig * 2;
            const float b0 = bias[col];
            const float b1 = bias[col + 1];
            const int r0 = m0 + wm + mi * 16 + gid;
            float2 v0 = make_float2(acc[mi][ni][0] + b0, acc[mi][ni][1] + b1);
            float2 v1 = make_float2(acc[mi][ni][2] + b0, acc[mi][ni][3] + b1);
            *reinterpret_cast<float2*>(C + (size_t)r0 * N + col)       = v0;
            *reinterpret_cast<float2*>(C + (size_t)(r0 + 8) * N + col) = v1;
        }
    }
}

// ---------------------------------------------------------------------------
// Per-(window, head) attention (unchanged from R1)
// ---------------------------------------------------------------------------
__global__ void __launch_bounds__(128)
window_attn_kernel(const float* __restrict__ mask,
                   const float* __restrict__ bias_table,
                   const int*   __restrict__ pos_index)
{
    __shared__ float sq[WN][WHD];
    __shared__ float sk[WN][WHD];
    __shared__ float sv[WN][WHD];
    __shared__ float sattn[WN][WN];

    const int bid = blockIdx.x;
    const int b   = bid >> 4;
    const int h   = bid & 15;
    const int t   = threadIdx.x;

    const float* qkv_base = g_qkv + (size_t)b * WN * (3 * WC) + h * WHD;

    for (int idx = t; idx < WN * WHD; idx += 128) {
        const int n = idx >> 5;
        const int d = idx & 31;
        const float* row = qkv_base + (size_t)n * (3 * WC) + d;
        sq[n][d] = row[0];
        sk[n][d] = row[WC];
        sv[n][d] = row[2 * WC];
    }
    __syncthreads();

    const float* mrow = mask + (size_t)(b & (WNW - 1)) * WN * WN;
    for (int e = t; e < WN * WN; e += 128) {
        const int i = e / WN;
        const int j = e - i * WN;
        float dot = 0.f;
        #pragma unroll
        for (int d = 0; d < WHD; d++) dot += sq[i][d] * sk[j][d];
        const float bq = bias_table[pos_index[e] * WH + h];
        sattn[i][j] = dot * SCALE + bq + mrow[e];
    }
    __syncthreads();

    const int warp = t >> 5, lane = t & 31;
    for (int i = warp; i < WN; i += 4) {
        float mx = -1e30f;
        for (int j = lane; j < WN; j += 32) mx = fmaxf(mx, sattn[i][j]);
        #pragma unroll
        for (int o = 16; o > 0; o >>= 1) mx = fmaxf(mx, __shfl_xor_sync(0xffffffffu, mx, o));
        float s = 0.f;
        for (int j = lane; j < WN; j += 32) {
            float e = expf(sattn[i][j] - mx);
            sattn[i][j] = e;
            s += e;
        }
        #pragma unroll
        for (int o = 16; o > 0; o >>= 1) s += __shfl_xor_sync(0xffffffffu, s, o);
        const float inv = 1.f / s;
        for (int j = lane; j < WN; j += 32) sattn[i][j] *= inv;
    }
    __syncthreads();

    for (int idx = t; idx < WN * WHD; idx += 128) {
        const int i = idx >> 5;
        const int d = idx & 31;
        float o = 0.f;
        #pragma unroll
        for (int j = 0; j < WN; j++) o += sattn[i][j] * sv[j][d];
        g_att[(size_t)(b * WN + i) * WC + h * WHD + d] = o;
    }
}

// ---------------------------------------------------------------------------
// Launch
// ---------------------------------------------------------------------------
extern "C" void kernel_launch(void* const* d_in, const int* in_sizes, int n_in,
                              void* d_out, int out_size)
{
    const float* x       = (const float*)d_in[0];
    const float* mask    = (const float*)d_in[1];
    const float* w_qkv   = (const float*)d_in[2];
    const float* b_qkv   = (const float*)d_in[3];
    const float* w_proj  = (const float*)d_in[4];
    const float* b_proj  = (const float*)d_in[5];
    const float* pbt     = (const float*)d_in[6];
    const int*   pos_idx = (const int*)d_in[7];
    float*       out     = (float*)d_out;

    float* qkv_buf;
    float* att_buf;
    cudaGetSymbolAddress((void**)&qkv_buf, g_qkv);
    cudaGetSymbolAddress((void**)&att_buf, g_att);

    // 1) qkv = x @ w_qkv + b_qkv   [200704, 1536]
    {
        dim3 grid((3 * WC) / BN, M_TOTAL / BM);   // (12, 1568)
        gemm_tf32_bias<<<grid, 256>>>(x, w_qkv, b_qkv, qkv_buf,
                                      M_TOTAL, 3 * WC, WC);
    }

    // 2) attention -> g_att [200704, 512]
    window_attn_kernel<<<WB * WH, 128>>>(mask, pbt, pos_idx);

    // 3) out = g_att @ w_proj + b_proj  [200704, 512]
    {
        dim3 grid(WC / BN, M_TOTAL / BM);          // (4, 1568)
        gemm_tf32_bias<<<grid, 256>>>(att_buf, w_proj, b_proj, out,
                                      M_TOTAL, WC, WC);
    }
}

// round 4
// speedup vs baseline: 1.8737x; 1.0002x over previous
#include <cuda_runtime.h>
#include <cuda_bf16.h>
#include <cstdint>

// ---------------------------------------------------------------------------
// Problem constants
// ---------------------------------------------------------------------------
#define WB   4096
#define WN   49
#define WC   512
#define WH   16
#define WHD  32
#define WNW  64
#define M_TOTAL (WB * WN)       // 200704
#define SCALE 0.17677669529663687f

// Scratch
__device__ float g_qkv[(size_t)M_TOTAL * (3 * WC)];
__device__ float g_att[(size_t)M_TOTAL * WC];

// ---------------------------------------------------------------------------
// TF32 tensor-core GEMM: C = A[M,K] @ B[K,N] + bias[N]
// CTA 128x128x16, 256 threads (8 warps, 2x4), warp tile 64x32,
// mma.sync m16n8k8 tf32, cp.async double-buffered smem.
// Requires M%128==0, N%128==0, K%16==0 (true for all our shapes).
// ---------------------------------------------------------------------------
#define BM 128
#define BN 128
#define BK 16
#define SA (BK + 4)    // 20 floats  — A smem row stride (conflict-free LDS)
#define SB (BN + 8)    // 136 floats — B smem row stride (conflict-free LDS)

__device__ __forceinline__ uint32_t f2tf32(float x) {
    uint32_t r;
    asm("cvt.rna.tf32.f32 %0, %1;" : "=r"(r) : "f"(x));
    return r;
}

__device__ __forceinline__ void cp16(uint32_t dst_smem, const float* src) {
    asm volatile("cp.async.cg.shared.global [%0], [%1], 16;"
                 :: "r"(dst_smem), "l"(src));
}

__device__ __forceinline__ void mma_tf32(float& c0, float& c1, float& c2, float& c3,
                                         uint32_t a0, uint32_t a1, uint32_t a2, uint32_t a3,
                                         uint32_t b0, uint32_t b1) {
    asm volatile(
        "mma.sync.aligned.m16n8k8.row.col.f32.tf32.tf32.f32 "
        "{%0,%1,%2,%3}, {%4,%5,%6,%7}, {%8,%9}, {%0,%1,%2,%3};"
        : "+f"(c0), "+f"(c1), "+f"(c2), "+f"(c3)
        : "r"(a0), "r"(a1), "r"(a2), "r"(a3), "r"(b0), "r"(b1));
}

__global__ void __launch_bounds__(256)
gemm_tf32_bias(const float* __restrict__ A, const float* __restrict__ B,
               const float* __restrict__ bias, float* __restrict__ C,
               int M, int N, int K)
{
    __shared__ float As[2][BM * SA];
    __shared__ float Bs[2][BK * SB];

    const int t    = threadIdx.x;
    const int warp = t >> 5;
    const int lane = t & 31;
    const int gid  = lane >> 2;   // 0..7
    const int tig  = lane & 3;    // 0..3

    const int m0 = blockIdx.y * BM;
    const int n0 = blockIdx.x * BN;

    const int wm = (warp >> 2) * 64;   // warp row offset in CTA tile
    const int wn = (warp & 3) * 32;    // warp col offset

    // --- global load mapping ---
    // A: two rows per thread (r, r+64), 4 consecutive k per thread
    const int ar  = t >> 2;            // 0..63
    const int ak  = (t & 3) * 4;       // 0,4,8,12
    // B: two rows per thread (br, br+8), 4 consecutive n per thread
    const int br  = t >> 5;            // 0..7
    const int bn  = (t & 31) * 4;      // 0..124

    const uint32_t sA_base = (uint32_t)__cvta_generic_to_shared(&As[0][0]);
    const uint32_t sB_base = (uint32_t)__cvta_generic_to_shared(&Bs[0][0]);
    const uint32_t sA_stage = BM * SA * 4u;
    const uint32_t sB_stage = BK * SB * 4u;

    const float* Ag = A + (size_t)(m0 + ar) * K + ak;
    const float* Bg = B + (size_t)br * N + n0 + bn;

    float acc[4][4][4];   // [mi][ni][c0..c3]
    #pragma unroll
    for (int mi = 0; mi < 4; mi++)
        #pragma unroll
        for (int ni = 0; ni < 4; ni++)
            #pragma unroll
            for (int c = 0; c < 4; c++) acc[mi][ni][c] = 0.f;

    const int iters = K / BK;

    // prologue: stage 0
    {
        cp16(sA_base + ((uint32_t)(ar * SA + ak) << 2),            Ag);
        cp16(sA_base + ((uint32_t)((ar + 64) * SA + ak) << 2),     Ag + (size_t)64 * K);
        cp16(sB_base + ((uint32_t)(br * SB + bn) << 2),            Bg);
        cp16(sB_base + ((uint32_t)((br + 8) * SB + bn) << 2),      Bg + (size_t)8 * N);
        asm volatile("cp.async.commit_group;");
    }

    for (int it = 0; it < iters; ++it) {
        asm volatile("cp.async.wait_group 0;");
        __syncthreads();

        if (it + 1 < iters) {
            const int k0 = (it + 1) * BK;
            const uint32_t st = ((it + 1) & 1);
            cp16(sA_base + st * sA_stage + ((uint32_t)(ar * SA + ak) << 2),
                 Ag + k0);
            cp16(sA_base + st * sA_stage + ((uint32_t)((ar + 64) * SA + ak) << 2),
                 Ag + (size_t)64 * K + k0);
            cp16(sB_base + st * sB_stage + ((uint32_t)(br * SB + bn) << 2),
                 Bg + (size_t)k0 * N);
            cp16(sB_base + st * sB_stage + ((uint32_t)((br + 8) * SB + bn) << 2),
                 Bg + (size_t)(k0 + 8) * N);
            asm volatile("cp.async.commit_group;");
        }

        const float* sA = As[it & 1];
        const float* sB = Bs[it & 1];

        #pragma unroll
        for (int kk = 0; kk < BK; kk += 8) {
            // A fragments: a0=A[gid][tig], a1=A[gid+8][tig], a2=A[gid][tig+4], a3=A[gid+8][tig+4]
            uint32_t af[4][4];
            #pragma unroll
            for (int mi = 0; mi < 4; mi++) {
                const int r = wm + mi * 16 + gid;
                af[mi][0] = f2tf32(sA[(r)     * SA + kk + tig]);
                af[mi][1] = f2tf32(sA[(r + 8) * SA + kk + tig]);
                af[mi][2] = f2tf32(sA[(r)     * SA + kk + tig + 4]);
                af[mi][3] = f2tf32(sA[(r + 8) * SA + kk + tig + 4]);
            }
            // B fragments: b0=B[tig][n], b1=B[tig+4][n], n = wn + ni*8 + gid
            uint32_t bf[4][2];
            #pragma unroll
            for (int ni = 0; ni < 4; ni++) {
                const int n = wn + ni * 8 + gid;
                bf[ni][0] = f2tf32(sB[(kk + tig)     * SB + n]);
                bf[ni][1] = f2tf32(sB[(kk + tig + 4) * SB + n]);
            }
            #pragma unroll
            for (int mi = 0; mi < 4; mi++)
                #pragma unroll
                for (int ni = 0; ni < 4; ni++)
                    mma_tf32(acc[mi][ni][0], acc[mi][ni][1],
                             acc[mi][ni][2], acc[mi][ni][3],
                             af[mi][0], af[mi][1], af[mi][2], af[mi][3],
                             bf[ni][0], bf[ni][1]);
        }
        // no trailing sync needed: next iter's wait+sync precedes buffer reuse
    }

    // epilogue: bias add + store (float2 per fragment half-row)
    #pragma unroll
    for (int mi = 0; mi < 4; mi++) {
        #pragma unroll
        for (int ni = 0; ni < 4; ni++) {
            const int col = n0 + wn + ni * 8 + tig * 2;
            const float b0 = bias[col];
            const float b1 = bias[col + 1];
            const int r0 = m0 + wm + mi * 16 + gid;
            float2 v0 = make_float2(acc[mi][ni][0] + b0, acc[mi][ni][1] + b1);
            float2 v1 = make_float2(acc[mi][ni][2] + b0, acc[mi][ni][3] + b1);
            *reinterpret_cast<float2*>(C + (size_t)r0 * N + col)       = v0;
            *reinterpret_cast<float2*>(C + (size_t)(r0 + 8) * N + col) = v1;
        }
    }
}

// ---------------------------------------------------------------------------
// Per-(window, head) attention (unchanged from R1)
// ---------------------------------------------------------------------------
__global__ void __launch_bounds__(128)
window_attn_kernel(const float* __restrict__ mask,
                   const float* __restrict__ bias_table,
                   const int*   __restrict__ pos_index)
{
    __shared__ float sq[WN][WHD];
    __shared__ float sk[WN][WHD];
    __shared__ float sv[WN][WHD];
    __shared__ float sattn[WN][WN];

    const int bid = blockIdx.x;
    const int b   = bid >> 4;
    const int h   = bid & 15;
    const int t   = threadIdx.x;

    const float* qkv_base = g_qkv + (size_t)b * WN * (3 * WC) + h * WHD;

    for (int idx = t; idx < WN * WHD; idx += 128) {
        const int n = idx >> 5;
        const int d = idx & 31;
        const float* row = qkv_base + (size_t)n * (3 * WC) + d;
        sq[n][d] = row[0];
        sk[n][d] = row[WC];
        sv[n][d] = row[2 * WC];
    }
    __syncthreads();

    const float* mrow = mask + (size_t)(b & (WNW - 1)) * WN * WN;
    for (int e = t; e < WN * WN; e += 128) {
        const int i = e / WN;
        const int j = e - i * WN;
        float dot = 0.f;
        #pragma unroll
        for (int d = 0; d < WHD; d++) dot += sq[i][d] * sk[j][d];
        const float bq = bias_table[pos_index[e] * WH + h];
        sattn[i][j] = dot * SCALE + bq + mrow[e];
    }
    __syncthreads();

    const int warp = t >> 5, lane = t & 31;
    for (int i = warp; i < WN; i += 4) {
        float mx = -1e30f;
        for (int j = lane; j < WN; j += 32) mx = fmaxf(mx, sattn[i][j]);
        #pragma unroll
        for (int o = 16; o > 0; o >>= 1) mx = fmaxf(mx, __shfl_xor_sync(0xffffffffu, mx, o));
        float s = 0.f;
        for (int j = lane; j < WN; j += 32) {
            float e = expf(sattn[i][j] - mx);
            sattn[i][j] = e;
            s += e;
        }
        #pragma unroll
        for (int o = 16; o > 0; o >>= 1) s += __shfl_xor_sync(0xffffffffu, s, o);
        const float inv = 1.f / s;
        for (int j = lane; j < WN; j += 32) sattn[i][j] *= inv;
    }
    __syncthreads();

    for (int idx = t; idx < WN * WHD; idx += 128) {
        const int i = idx >> 5;
        const int d = idx & 31;
        float o = 0.f;
        #pragma unroll
        for (int j = 0; j < WN; j++) o += sattn[i][j] * sv[j][d];
        g_att[(size_t)(b * WN + i) * WC + h * WHD + d] = o;
    }
}

// ---------------------------------------------------------------------------
// Launch
// ---------------------------------------------------------------------------
extern "C" void kernel_launch(void* const* d_in, const int* in_sizes, int n_in,
                              void* d_out, int out_size)
{
    const float* x       = (const float*)d_in[0];
    const float* mask    = (const float*)d_in[1];
    const float* w_qkv   = (const float*)d_in[2];
    const float* b_qkv   = (const float*)d_in[3];
    const float* w_proj  = (const float*)d_in[4];
    const float* b_proj  = (const float*)d_in[5];
    const float* pbt     = (const float*)d_in[6];
    const int*   pos_idx = (const int*)d_in[7];
    float*       out     = (float*)d_out;

    float* qkv_buf;
    float* att_buf;
    cudaGetSymbolAddress((void**)&qkv_buf, g_qkv);
    cudaGetSymbolAddress((void**)&att_buf, g_att);

    // 1) qkv = x @ w_qkv + b_qkv   [200704, 1536]
    {
        dim3 grid((3 * WC) / BN, M_TOTAL / BM);   // (12, 1568)
        gemm_tf32_bias<<<grid, 256>>>(x, w_qkv, b_qkv, qkv_buf,
                                      M_TOTAL, 3 * WC, WC);
    }

    // 2) attention -> g_att [200704, 512]
    window_attn_kernel<<<WB * WH, 128>>>(mask, pbt, pos_idx);

    // 3) out = g_att @ w_proj + b_proj  [200704, 512]
    {
        dim3 grid(WC / BN, M_TOTAL / BM);          // (4, 1568)
        gemm_tf32_bias<<<grid, 256>>>(att_buf, w_proj, b_proj, out,
                                      M_TOTAL, WC, WC);
    }
}

// round 5
// speedup vs baseline: 1.8740x; 1.0002x over previous
#include <cuda_runtime.h>
#include <cuda_bf16.h>
#include <cstdint>

// ---------------------------------------------------------------------------
// Problem constants
// ---------------------------------------------------------------------------
#define WB   4096
#define WN   49
#define WC   512
#define WH   16
#define WHD  32
#define WNW  64
#define M_TOTAL (WB * WN)       // 200704
#define SCALE 0.17677669529663687f

// Scratch
__device__ float g_qkv[(size_t)M_TOTAL * (3 * WC)];
__device__ float g_att[(size_t)M_TOTAL * WC];

// ---------------------------------------------------------------------------
// TF32 tensor-core GEMM: C = A[M,K] @ B[K,N] + bias[N]
// CTA 128x128x16, 256 threads (8 warps, 2x4), warp tile 64x32,
// mma.sync m16n8k8 tf32, cp.async double-buffered smem.
// Requires M%128==0, N%128==0, K%16==0 (true for all our shapes).
// ---------------------------------------------------------------------------
#define BM 128
#define BN 128
#define BK 16
#define SA (BK + 4)    // 20 floats  — A smem row stride (conflict-free LDS)
#define SB (BN + 8)    // 136 floats — B smem row stride (conflict-free LDS)

__device__ __forceinline__ uint32_t f2tf32(float x) {
    uint32_t r;
    asm("cvt.rna.tf32.f32 %0, %1;" : "=r"(r) : "f"(x));
    return r;
}

__device__ __forceinline__ void cp16(uint32_t dst_smem, const float* src) {
    asm volatile("cp.async.cg.shared.global [%0], [%1], 16;"
                 :: "r"(dst_smem), "l"(src));
}

__device__ __forceinline__ void mma_tf32(float& c0, float& c1, float& c2, float& c3,
                                         uint32_t a0, uint32_t a1, uint32_t a2, uint32_t a3,
                                         uint32_t b0, uint32_t b1) {
    asm volatile(
        "mma.sync.aligned.m16n8k8.row.col.f32.tf32.tf32.f32 "
        "{%0,%1,%2,%3}, {%4,%5,%6,%7}, {%8,%9}, {%0,%1,%2,%3};"
        : "+f"(c0), "+f"(c1), "+f"(c2), "+f"(c3)
        : "r"(a0), "r"(a1), "r"(a2), "r"(a3), "r"(b0), "r"(b1));
}

__global__ void __launch_bounds__(256)
gemm_tf32_bias(const float* __restrict__ A, const float* __restrict__ B,
               const float* __restrict__ bias, float* __restrict__ C,
               int M, int N, int K)
{
    __shared__ float As[2][BM * SA];
    __shared__ float Bs[2][BK * SB];

    const int t    = threadIdx.x;
    const int warp = t >> 5;
    const int lane = t & 31;
    const int gid  = lane >> 2;   // 0..7
    const int tig  = lane & 3;    // 0..3

    const int m0 = blockIdx.y * BM;
    const int n0 = blockIdx.x * BN;

    const int wm = (warp >> 2) * 64;   // warp row offset in CTA tile
    const int wn = (warp & 3) * 32;    // warp col offset

    // --- global load mapping ---
    // A: two rows per thread (r, r+64), 4 consecutive k per thread
    const int ar  = t >> 2;            // 0..63
    const int ak  = (t & 3) * 4;       // 0,4,8,12
    // B: two rows per thread (br, br+8), 4 consecutive n per thread
    const int br  = t >> 5;            // 0..7
    const int bn  = (t & 31) * 4;      // 0..124

    const uint32_t sA_base = (uint32_t)__cvta_generic_to_shared(&As[0][0]);
    const uint32_t sB_base = (uint32_t)__cvta_generic_to_shared(&Bs[0][0]);
    const uint32_t sA_stage = BM * SA * 4u;
    const uint32_t sB_stage = BK * SB * 4u;

    const float* Ag = A + (size_t)(m0 + ar) * K + ak;
    const float* Bg = B + (size_t)br * N + n0 + bn;

    float acc[4][4][4];   // [mi][ni][c0..c3]
    #pragma unroll
    for (int mi = 0; mi < 4; mi++)
        #pragma unroll
        for (int ni = 0; ni < 4; ni++)
            #pragma unroll
            for (int c = 0; c < 4; c++) acc[mi][ni][c] = 0.f;

    const int iters = K / BK;

    // prologue: stage 0
    {
        cp16(sA_base + ((uint32_t)(ar * SA + ak) << 2),            Ag);
        cp16(sA_base + ((uint32_t)((ar + 64) * SA + ak) << 2),     Ag + (size_t)64 * K);
        cp16(sB_base + ((uint32_t)(br * SB + bn) << 2),            Bg);
        cp16(sB_base + ((uint32_t)((br + 8) * SB + bn) << 2),      Bg + (size_t)8 * N);
        asm volatile("cp.async.commit_group;");
    }

    for (int it = 0; it < iters; ++it) {
        asm volatile("cp.async.wait_group 0;");
        __syncthreads();

        if (it + 1 < iters) {
            const int k0 = (it + 1) * BK;
            const uint32_t st = ((it + 1) & 1);
            cp16(sA_base + st * sA_stage + ((uint32_t)(ar * SA + ak) << 2),
                 Ag + k0);
            cp16(sA_base + st * sA_stage + ((uint32_t)((ar + 64) * SA + ak) << 2),
                 Ag + (size_t)64 * K + k0);
            cp16(sB_base + st * sB_stage + ((uint32_t)(br * SB + bn) << 2),
                 Bg + (size_t)k0 * N);
            cp16(sB_base + st * sB_stage + ((uint32_t)((br + 8) * SB + bn) << 2),
                 Bg + (size_t)(k0 + 8) * N);
            asm volatile("cp.async.commit_group;");
        }

        const float* sA = As[it & 1];
        const float* sB = Bs[it & 1];

        #pragma unroll
        for (int kk = 0; kk < BK; kk += 8) {
            // A fragments: a0=A[gid][tig], a1=A[gid+8][tig], a2=A[gid][tig+4], a3=A[gid+8][tig+4]
            uint32_t af[4][4];
            #pragma unroll
            for (int mi = 0; mi < 4; mi++) {
                const int r = wm + mi * 16 + gid;
                af[mi][0] = f2tf32(sA[(r)     * SA + kk + tig]);
                af[mi][1] = f2tf32(sA[(r + 8) * SA + kk + tig]);
                af[mi][2] = f2tf32(sA[(r)     * SA + kk + tig + 4]);
                af[mi][3] = f2tf32(sA[(r + 8) * SA + kk + tig + 4]);
            }
            // B fragments: b0=B[tig][n], b1=B[tig+4][n], n = wn + ni*8 + gid
            uint32_t bf[4][2];
            #pragma unroll
            for (int ni = 0; ni < 4; ni++) {
                const int n = wn + ni * 8 + gid;
                bf[ni][0] = f2tf32(sB[(kk + tig)     * SB + n]);
                bf[ni][1] = f2tf32(sB[(kk + tig + 4) * SB + n]);
            }
            #pragma unroll
            for (int mi = 0; mi < 4; mi++)
                #pragma unroll
                for (int ni = 0; ni < 4; ni++)
                    mma_tf32(acc[mi][ni][0], acc[mi][ni][1],
                             acc[mi][ni][2], acc[mi][ni][3],
                             af[mi][0], af[mi][1], af[mi][2], af[mi][3],
                             bf[ni][0], bf[ni][1]);
        }
        // no trailing sync needed: next iter's wait+sync precedes buffer reuse
    }

    // epilogue: bias add + store (float2 per fragment half-row)
    #pragma unroll
    for (int mi = 0; mi < 4; mi++) {
        #pragma unroll
        for (int ni = 0; ni < 4; ni++) {
            const int col = n0 + wn + ni * 8 + tig * 2;
            const float b0 = bias[col];
            const float b1 = bias[col + 1];
            const int r0 = m0 + wm + mi * 16 + gid;
            float2 v0 = make_float2(acc[mi][ni][0] + b0, acc[mi][ni][1] + b1);
            float2 v1 = make_float2(acc[mi][ni][2] + b0, acc[mi][ni][3] + b1);
            *reinterpret_cast<float2*>(C + (size_t)r0 * N + col)       = v0;
            *reinterpret_cast<float2*>(C + (size_t)(r0 + 8) * N + col) = v1;
        }
    }
}

// ---------------------------------------------------------------------------
// Per-(window, head) attention (unchanged from R1)
// ---------------------------------------------------------------------------
__global__ void __launch_bounds__(128)
window_attn_kernel(const float* __restrict__ mask,
                   const float* __restrict__ bias_table,
                   const int*   __restrict__ pos_index)
{
    __shared__ float sq[WN][WHD];
    __shared__ float sk[WN][WHD];
    __shared__ float sv[WN][WHD];
    __shared__ float sattn[WN][WN];

    const int bid = blockIdx.x;
    const int b   = bid >> 4;
    const int h   = bid & 15;
    const int t   = threadIdx.x;

    const float* qkv_base = g_qkv + (size_t)b * WN * (3 * WC) + h * WHD;

    for (int idx = t; idx < WN * WHD; idx += 128) {
        const int n = idx >> 5;
        const int d = idx & 31;
        const float* row = qkv_base + (size_t)n * (3 * WC) + d;
        sq[n][d] = row[0];
        sk[n][d] = row[WC];
        sv[n][d] = row[2 * WC];
    }
    __syncthreads();

    const float* mrow = mask + (size_t)(b & (WNW - 1)) * WN * WN;
    for (int e = t; e < WN * WN; e += 128) {
        const int i = e / WN;
        const int j = e - i * WN;
        float dot = 0.f;
        #pragma unroll
        for (int d = 0; d < WHD; d++) dot += sq[i][d] * sk[j][d];
        const float bq = bias_table[pos_index[e] * WH + h];
        sattn[i][j] = dot * SCALE + bq + mrow[e];
    }
    __syncthreads();

    const int warp = t >> 5, lane = t & 31;
    for (int i = warp; i < WN; i += 4) {
        float mx = -1e30f;
        for (int j = lane; j < WN; j += 32) mx = fmaxf(mx, sattn[i][j]);
        #pragma unroll
        for (int o = 16; o > 0; o >>= 1) mx = fmaxf(mx, __shfl_xor_sync(0xffffffffu, mx, o));
        float s = 0.f;
        for (int j = lane; j < WN; j += 32) {
            float e = expf(sattn[i][j] - mx);
            sattn[i][j] = e;
            s += e;
        }
        #pragma unroll
        for (int o = 16; o > 0; o >>= 1) s += __shfl_xor_sync(0xffffffffu, s, o);
        const float inv = 1.f / s;
        for (int j = lane; j < WN; j += 32) sattn[i][j] *= inv;
    }
    __syncthreads();

    for (int idx = t; idx < WN * WHD; idx += 128) {
        const int i = idx >> 5;
        const int d = idx & 31;
        float o = 0.f;
        #pragma unroll
        for (int j = 0; j < WN; j++) o += sattn[i][j] * sv[j][d];
        g_att[(size_t)(b * WN + i) * WC + h * WHD + d] = o;
    }
}

// ---------------------------------------------------------------------------
// Launch
// ---------------------------------------------------------------------------
extern "C" void kernel_launch(void* const* d_in, const int* in_sizes, int n_in,
                              void* d_out, int out_size)
{
    const float* x       = (const float*)d_in[0];
    const float* mask    = (const float*)d_in[1];
    const float* w_qkv   = (const float*)d_in[2];
    const float* b_qkv   = (const float*)d_in[3];
    const float* w_proj  = (const float*)d_in[4];
    const float* b_proj  = (const float*)d_in[5];
    const float* pbt     = (const float*)d_in[6];
    const int*   pos_idx = (const int*)d_in[7];
    float*       out     = (float*)d_out;

    float* qkv_buf;
    float* att_buf;
    cudaGetSymbolAddress((void**)&qkv_buf, g_qkv);
    cudaGetSymbolAddress((void**)&att_buf, g_att);

    // 1) qkv = x @ w_qkv + b_qkv   [200704, 1536]
    {
        dim3 grid((3 * WC) / BN, M_TOTAL / BM);   // (12, 1568)
        gemm_tf32_bias<<<grid, 256>>>(x, w_qkv, b_qkv, qkv_buf,
                                      M_TOTAL, 3 * WC, WC);
    }

    // 2) attention -> g_att [200704, 512]
    window_attn_kernel<<<WB * WH, 128>>>(mask, pbt, pos_idx);

    // 3) out = g_att @ w_proj + b_proj  [200704, 512]
    {
        dim3 grid(WC / BN, M_TOTAL / BM);          // (4, 1568)
        gemm_tf32_bias<<<grid, 256>>>(att_buf, w_proj, b_proj, out,
                                      M_TOTAL, WC, WC);
    }
}

// round 6
// speedup vs baseline: 1.8748x; 1.0004x over previous
#include <cuda_runtime.h>
#include <cuda_bf16.h>
#include <cstdint>

// ---------------------------------------------------------------------------
// Problem constants
// ---------------------------------------------------------------------------
#define WB   4096
#define WN   49
#define WC   512
#define WH   16
#define WHD  32
#define WNW  64
#define M_TOTAL (WB * WN)       // 200704
#define SCALE 0.17677669529663687f

// Scratch
__device__ float g_qkv[(size_t)M_TOTAL * (3 * WC)];
__device__ float g_att[(size_t)M_TOTAL * WC];

// ---------------------------------------------------------------------------
// TF32 tensor-core GEMM: C = A[M,K] @ B[K,N] + bias[N]
// CTA 128x128x16, 256 threads (8 warps, 2x4), warp tile 64x32,
// mma.sync m16n8k8 tf32, cp.async double-buffered smem.
// Requires M%128==0, N%128==0, K%16==0 (true for all our shapes).
// ---------------------------------------------------------------------------
#define BM 128
#define BN 128
#define BK 16
#define SA (BK + 4)    // 20 floats  — A smem row stride (conflict-free LDS)
#define SB (BN + 8)    // 136 floats — B smem row stride (conflict-free LDS)

__device__ __forceinline__ uint32_t f2tf32(float x) {
    uint32_t r;
    asm("cvt.rna.tf32.f32 %0, %1;" : "=r"(r) : "f"(x));
    return r;
}

__device__ __forceinline__ void cp16(uint32_t dst_smem, const float* src) {
    asm volatile("cp.async.cg.shared.global [%0], [%1], 16;"
                 :: "r"(dst_smem), "l"(src));
}

__device__ __forceinline__ void mma_tf32(float& c0, float& c1, float& c2, float& c3,
                                         uint32_t a0, uint32_t a1, uint32_t a2, uint32_t a3,
                                         uint32_t b0, uint32_t b1) {
    asm volatile(
        "mma.sync.aligned.m16n8k8.row.col.f32.tf32.tf32.f32 "
        "{%0,%1,%2,%3}, {%4,%5,%6,%7}, {%8,%9}, {%0,%1,%2,%3};"
        : "+f"(c0), "+f"(c1), "+f"(c2), "+f"(c3)
        : "r"(a0), "r"(a1), "r"(a2), "r"(a3), "r"(b0), "r"(b1));
}

__global__ void __launch_bounds__(256)
gemm_tf32_bias(const float* __restrict__ A, const float* __restrict__ B,
               const float* __restrict__ bias, float* __restrict__ C,
               int M, int N, int K)
{
    __shared__ float As[2][BM * SA];
    __shared__ float Bs[2][BK * SB];

    const int t    = threadIdx.x;
    const int warp = t >> 5;
    const int lane = t & 31;
    const int gid  = lane >> 2;   // 0..7
    const int tig  = lane & 3;    // 0..3

    const int m0 = blockIdx.y * BM;
    const int n0 = blockIdx.x * BN;

    const int wm = (warp >> 2) * 64;   // warp row offset in CTA tile
    const int wn = (warp & 3) * 32;    // warp col offset

    // --- global load mapping ---
    // A: two rows per thread (r, r+64), 4 consecutive k per thread
    const int ar  = t >> 2;            // 0..63
    const int ak  = (t & 3) * 4;       // 0,4,8,12
    // B: two rows per thread (br, br+8), 4 consecutive n per thread
    const int br  = t >> 5;            // 0..7
    const int bn  = (t & 31) * 4;      // 0..124

    const uint32_t sA_base = (uint32_t)__cvta_generic_to_shared(&As[0][0]);
    const uint32_t sB_base = (uint32_t)__cvta_generic_to_shared(&Bs[0][0]);
    const uint32_t sA_stage = BM * SA * 4u;
    const uint32_t sB_stage = BK * SB * 4u;

    const float* Ag = A + (size_t)(m0 + ar) * K + ak;
    const float* Bg = B + (size_t)br * N + n0 + bn;

    float acc[4][4][4];   // [mi][ni][c0..c3]
    #pragma unroll
    for (int mi = 0; mi < 4; mi++)
        #pragma unroll
        for (int ni = 0; ni < 4; ni++)
            #pragma unroll
            for (int c = 0; c < 4; c++) acc[mi][ni][c] = 0.f;

    const int iters = K / BK;

    // prologue: stage 0
    {
        cp16(sA_base + ((uint32_t)(ar * SA + ak) << 2),            Ag);
        cp16(sA_base + ((uint32_t)((ar + 64) * SA + ak) << 2),     Ag + (size_t)64 * K);
        cp16(sB_base + ((uint32_t)(br * SB + bn) << 2),            Bg);
        cp16(sB_base + ((uint32_t)((br + 8) * SB + bn) << 2),      Bg + (size_t)8 * N);
        asm volatile("cp.async.commit_group;");
    }

    for (int it = 0; it < iters; ++it) {
        asm volatile("cp.async.wait_group 0;");
        __syncthreads();

        if (it + 1 < iters) {
            const int k0 = (it + 1) * BK;
            const uint32_t st = ((it + 1) & 1);
            cp16(sA_base + st * sA_stage + ((uint32_t)(ar * SA + ak) << 2),
                 Ag + k0);
            cp16(sA_base + st * sA_stage + ((uint32_t)((ar + 64) * SA + ak) << 2),
                 Ag + (size_t)64 * K + k0);
            cp16(sB_base + st * sB_stage + ((uint32_t)(br * SB + bn) << 2),
                 Bg + (size_t)k0 * N);
            cp16(sB_base + st * sB_stage + ((uint32_t)((br + 8) * SB + bn) << 2),
                 Bg + (size_t)(k0 + 8) * N);
            asm volatile("cp.async.commit_group;");
        }

        const float* sA = As[it & 1];
        const float* sB = Bs[it & 1];

        #pragma unroll
        for (int kk = 0; kk < BK; kk += 8) {
            // A fragments: a0=A[gid][tig], a1=A[gid+8][tig], a2=A[gid][tig+4], a3=A[gid+8][tig+4]
            uint32_t af[4][4];
            #pragma unroll
            for (int mi = 0; mi < 4; mi++) {
                const int r = wm + mi * 16 + gid;
                af[mi][0] = f2tf32(sA[(r)     * SA + kk + tig]);
                af[mi][1] = f2tf32(sA[(r + 8) * SA + kk + tig]);
                af[mi][2] = f2tf32(sA[(r)     * SA + kk + tig + 4]);
                af[mi][3] = f2tf32(sA[(r + 8) * SA + kk + tig + 4]);
            }
            // B fragments: b0=B[tig][n], b1=B[tig+4][n], n = wn + ni*8 + gid
            uint32_t bf[4][2];
            #pragma unroll
            for (int ni = 0; ni < 4; ni++) {
                const int n = wn + ni * 8 + gid;
                bf[ni][0] = f2tf32(sB[(kk + tig)     * SB + n]);
                bf[ni][1] = f2tf32(sB[(kk + tig + 4) * SB + n]);
            }
            #pragma unroll
            for (int mi = 0; mi < 4; mi++)
                #pragma unroll
                for (int ni = 0; ni < 4; ni++)
                    mma_tf32(acc[mi][ni][0], acc[mi][ni][1],
                             acc[mi][ni][2], acc[mi][ni][3],
                             af[mi][0], af[mi][1], af[mi][2], af[mi][3],
                             bf[ni][0], bf[ni][1]);
        }
        // no trailing sync needed: next iter's wait+sync precedes buffer reuse
    }

    // epilogue: bias add + store (float2 per fragment half-row)
    #pragma unroll
    for (int mi = 0; mi < 4; mi++) {
        #pragma unroll
        for (int ni = 0; ni < 4; ni++) {
            const int col = n0 + wn + ni * 8 + tig * 2;
            const float b0 = bias[col];
            const float b1 = bias[col + 1];
            const int r0 = m0 + wm + mi * 16 + gid;
            float2 v0 = make_float2(acc[mi][ni][0] + b0, acc[mi][ni][1] + b1);
            float2 v1 = make_float2(acc[mi][ni][2] + b0, acc[mi][ni][3] + b1);
            *reinterpret_cast<float2*>(C + (size_t)r0 * N + col)       = v0;
            *reinterpret_cast<float2*>(C + (size_t)(r0 + 8) * N + col) = v1;
        }
    }
}

// ---------------------------------------------------------------------------
// Per-(window, head) attention (unchanged from R1)
// ---------------------------------------------------------------------------
__global__ void __launch_bounds__(128)
window_attn_kernel(const float* __restrict__ mask,
                   const float* __restrict__ bias_table,
                   const int*   __restrict__ pos_index)
{
    __shared__ float sq[WN][WHD];
    __shared__ float sk[WN][WHD];
    __shared__ float sv[WN][WHD];
    __shared__ float sattn[WN][WN];

    const int bid = blockIdx.x;
    const int b   = bid >> 4;
    const int h   = bid & 15;
    const int t   = threadIdx.x;

    const float* qkv_base = g_qkv + (size_t)b * WN * (3 * WC) + h * WHD;

    for (int idx = t; idx < WN * WHD; idx += 128) {
        const int n = idx >> 5;
        const int d = idx & 31;
        const float* row = qkv_base + (size_t)n * (3 * WC) + d;
        sq[n][d] = row[0];
        sk[n][d] = row[WC];
        sv[n][d] = row[2 * WC];
    }
    __syncthreads();

    const float* mrow = mask + (size_t)(b & (WNW - 1)) * WN * WN;
    for (int e = t; e < WN * WN; e += 128) {
        const int i = e / WN;
        const int j = e - i * WN;
        float dot = 0.f;
        #pragma unroll
        for (int d = 0; d < WHD; d++) dot += sq[i][d] * sk[j][d];
        const float bq = bias_table[pos_index[e] * WH + h];
        sattn[i][j] = dot * SCALE + bq + mrow[e];
    }
    __syncthreads();

    const int warp = t >> 5, lane = t & 31;
    for (int i = warp; i < WN; i += 4) {
        float mx = -1e30f;
        for (int j = lane; j < WN; j += 32) mx = fmaxf(mx, sattn[i][j]);
        #pragma unroll
        for (int o = 16; o > 0; o >>= 1) mx = fmaxf(mx, __shfl_xor_sync(0xffffffffu, mx, o));
        float s = 0.f;
        for (int j = lane; j < WN; j += 32) {
            float e = expf(sattn[i][j] - mx);
            sattn[i][j] = e;
            s += e;
        }
        #pragma unroll
        for (int o = 16; o > 0; o >>= 1) s += __shfl_xor_sync(0xffffffffu, s, o);
        const float inv = 1.f / s;
        for (int j = lane; j < WN; j += 32) sattn[i][j] *= inv;
    }
    __syncthreads();

    for (int idx = t; idx < WN * WHD; idx += 128) {
        const int i = idx >> 5;
        const int d = idx & 31;
        float o = 0.f;
        #pragma unroll
        for (int j = 0; j < WN; j++) o += sattn[i][j] * sv[j][d];
        g_att[(size_t)(b * WN + i) * WC + h * WHD + d] = o;
    }
}

// ---------------------------------------------------------------------------
// Launch
// ---------------------------------------------------------------------------
extern "C" void kernel_launch(void* const* d_in, const int* in_sizes, int n_in,
                              void* d_out, int out_size)
{
    const float* x       = (const float*)d_in[0];
    const float* mask    = (const float*)d_in[1];
    const float* w_qkv   = (const float*)d_in[2];
    const float* b_qkv   = (const float*)d_in[3];
    const float* w_proj  = (const float*)d_in[4];
    const float* b_proj  = (const float*)d_in[5];
    const float* pbt     = (const float*)d_in[6];
    const int*   pos_idx = (const int*)d_in[7];
    float*       out     = (float*)d_out;

    float* qkv_buf;
    float* att_buf;
    cudaGetSymbolAddress((void**)&qkv_buf, g_qkv);
    cudaGetSymbolAddress((void**)&att_buf, g_att);

    // 1) qkv = x @ w_qkv + b_qkv   [200704, 1536]
    {
        dim3 grid((3 * WC) / BN, M_TOTAL / BM);   // (12, 1568)
        gemm_tf32_bias<<<grid, 256>>>(x, w_qkv, b_qkv, qkv_buf,
                                      M_TOTAL, 3 * WC, WC);
    }

    // 2) attention -> g_att [200704, 512]
    window_attn_kernel<<<WB * WH, 128>>>(mask, pbt, pos_idx);

    // 3) out = g_att @ w_proj + b_proj  [200704, 512]
    {
        dim3 grid(WC / BN, M_TOTAL / BM);          // (4, 1568)
        gemm_tf32_bias<<<grid, 256>>>(att_buf, w_proj, b_proj, out,
                                      M_TOTAL, WC, WC);
    }
}